// round 10
// baseline (speedup 1.0000x reference)
#include <cuda_runtime.h>

#define Bn   8
#define Tn   1024
#define Cn   768
#define Hn   12
#define HIDn 1536
#define Mn   16
#define Pn   4
#define PREn 20
#define TAn  1044
#define SLICES 16
#define NSTG 3

// ---------------- scratch (device globals; no cudaMalloc allowed) ----------------
__device__ float g_q   [Bn*Tn*Cn];
__device__ float g_hbuf[Bn*Tn*HIDn];
__device__ float g_mem [Bn*Tn*Cn];
__device__ float g_pool[Bn*Mn*Cn];
__device__ float g_retr[Bn*Mn*Cn];
__device__ float g_xa  [Bn*TAn*Cn];
__device__ float g_hln [Bn*TAn*Cn];
__device__ float g_qkv [Bn*TAn*3*Cn];
__device__ float g_att [Bn*Hn*TAn*TAn];   // ~418MB
__device__ float g_y   [Bn*TAn*Cn];
__device__ float g_fc  [Bn*TAn*4*Cn];
__device__ float g_o   [Bn*Tn*Cn];
__device__ float g_key [Bn*Tn*Cn];
__device__ float g_val [Bn*Tn*Cn];
__device__ float g_pre [Bn*Tn*HIDn];
__device__ float g_hh  [Bn*Tn*HIDn];
__device__ float g_dpr [Bn*Tn*Cn];
__device__ float g_dhh [Bn*Tn*HIDn];
__device__ float g_p0  [SLICES*Bn*HIDn];
__device__ float g_p1  [SLICES*Bn*Cn];

// ---------------- generic strided batched GEMM params ----------------
struct GP {
    const float* A; const float* Bm; float* O; float* O2;
    const float* bias; const float* aux; const float* aux2;
    int M, N, K, binner;
    long long sAm, sAk, bA, bA2;
    long long sBk, sBn, bB, bB2;
    long long sOm, sOn, bO, bO2;
    long long bBias;
    int mode, prefix, tri;
    float scale;
};
// modes: 0=bias 1=silu(+pre->O2) 2=gelu 3=attn scale+mask 4=residual-add
//        5=dpred 6=silu-bwd(aux=pre) 7=momentum update (aux=mem, aux2=mom, O=nw, O2=nmom)
// tri: 1=skip fully-masked blocks (scores), 2=cap K at m0+128 (attn y)

__device__ __forceinline__ unsigned f2tf(float x) {
    unsigned r;
    asm("cvt.rna.tf32.f32 %0, %1;" : "=r"(r) : "f"(x));
    return r;
}

__device__ __forceinline__ void mma_tf32(float* c, const unsigned* a, const unsigned* b) {
    asm volatile(
        "mma.sync.aligned.m16n8k8.row.col.f32.tf32.tf32.f32 "
        "{%0,%1,%2,%3}, {%4,%5,%6,%7}, {%8,%9}, {%0,%1,%2,%3};\n"
        : "+f"(c[0]), "+f"(c[1]), "+f"(c[2]), "+f"(c[3])
        : "r"(a[0]), "r"(a[1]), "r"(a[2]), "r"(a[3]), "r"(b[0]), "r"(b[1]));
}

__device__ __forceinline__ void cp16(float* dst, const float* src, bool pred) {
    unsigned d = (unsigned)__cvta_generic_to_shared(dst);
    int sz = pred ? 16 : 0;
    asm volatile("cp.async.cg.shared.global [%0], [%1], 16, %2;\n"
                 :: "r"(d), "l"(src), "r"(sz));
}
#define CP_COMMIT() asm volatile("cp.async.commit_group;\n" ::)

__device__ __forceinline__ void epi_write(const GP& p, int m, int n, float v,
                                          long long offO, long long offBias) {
    if (m >= p.M || n >= p.N) return;
    long long o = offO + (long long)m * p.sOm + (long long)n * p.sOn;
    float bsv = p.bias ? p.bias[offBias + n] : 0.f;
    switch (p.mode) {
        case 0: p.O[o] = v + bsv; break;
        case 1: { float z = v + bsv; if (p.O2) p.O2[o] = z;
                  float sg = 1.f / (1.f + __expf(-z)); p.O[o] = z * sg; } break;
        case 2: { float z = v + bsv; p.O[o] = 0.5f * z * (1.f + erff(z * 0.70710678118f)); } break;
        case 3: { float z = v * p.scale; if (m >= p.prefix && n > m) z = -1e30f; p.O[o] = z; } break;
        case 4: p.O[o] = p.aux[o] + v + bsv; break;
        case 5: p.O[o] = (v + bsv - p.aux[o]) * p.scale; break;
        case 6: { float z = p.aux[o]; float sg = 1.f / (1.f + __expf(-z));
                  p.O[o] = v * sg * (1.f + z * (1.f - sg)); } break;
        case 7: { float nm = 0.9f * p.aux2[o] + v; p.O2[o] = nm;
                  p.O[o] = 0.999f * p.aux[o] - 0.01f * nm; } break;
    }
}

// ---- tf32 tensor-core GEMM: 128x128 block, k-tile 8, 8 warps, cp.async 3-stage ----
// Orientation-matched smem layouts (both fit in 1536 floats / stage):
//   k-contiguous operand : row layout [128][12] (12-float row stride -> conflict-free frags)
//   m/n-contiguous       : col layout [8][132]
__global__ void __launch_bounds__(256, 2) gemm_tc(GP p) {
    __shared__ float smemA[NSTG][1536];
    __shared__ float smemB[NSTG][1536];
    int bz = blockIdx.z;
    int bo = bz / p.binner, bi = bz % p.binner;
    const float* Ap = p.A  + (long long)bo * p.bA + (long long)bi * p.bA2;
    const float* Bp = p.Bm + (long long)bo * p.bB + (long long)bi * p.bB2;
    int m0 = blockIdx.y * 128, n0 = blockIdx.x * 128;

    // triangular-mask shortcuts
    if (p.tri == 1 && m0 > 0 && n0 >= m0 + 128) return;
    int Keff = p.K;
    if (p.tri == 2 && m0 > 0 && m0 + 128 < Keff) Keff = m0 + 128;

    int tid = threadIdx.x;
    int warp = tid >> 5, lane = tid & 31;
    int wm = warp & 1, wn = warp >> 1;      // warp tile: 64 (m) x 32 (n)
    int lq = lane >> 2, lr = lane & 3;

    float acc[4][4][4];
#pragma unroll
    for (int i = 0; i < 4; i++)
#pragma unroll
        for (int j = 0; j < 4; j++)
#pragma unroll
            for (int r = 0; r < 4; r++) acc[i][j][r] = 0.f;

    const bool aK = (p.sAk == 1);     // A contiguous along k
    const bool bN = (p.sBn == 1);     // B contiguous along n

    auto issueA = [&](int k0, int stg) {
        float* dst = smemA[stg];
        if (aK) {                               // row layout [128][12]
            int row = tid >> 1, kv = (tid & 1) * 4;
            int gm = m0 + row, gk = k0 + kv;
            bool ok = (gm < p.M) && (gk < Keff);
            const float* src = ok ? (Ap + (long long)gm * p.sAm + gk) : Ap;
            cp16(&dst[row * 12 + kv], src, ok);
        } else {                                // col layout [8][132]
            int kr = tid >> 5, mv = (tid & 31) * 4;
            int gk = k0 + kr, gm = m0 + mv;
            bool ok = (gk < Keff) && (gm < p.M);
            const float* src = ok ? (Ap + (long long)gm * p.sAm + (long long)gk * p.sAk) : Ap;
            cp16(&dst[kr * 132 + mv], src, ok);
        }
    };
    auto issueB = [&](int k0, int stg) {
        float* dst = smemB[stg];
        if (bN) {                               // col layout [8][132]
            int kr = tid >> 5, nv = (tid & 31) * 4;
            int gk = k0 + kr, gn = n0 + nv;
            bool ok = (gk < Keff) && (gn < p.N);
            const float* src = ok ? (Bp + (long long)gk * p.sBk + gn) : Bp;
            cp16(&dst[kr * 132 + nv], src, ok);
        } else {                                // row layout [128][12]
            int row = tid >> 1, kv = (tid & 1) * 4;
            int gn = n0 + row, gk = k0 + kv;
            bool ok = (gn < p.N) && (gk < Keff);
            const float* src = ok ? (Bp + (long long)gk * p.sBk + (long long)gn * p.sBn) : Bp;
            cp16(&dst[row * 12 + kv], src, ok);
        }
    };

    int nk = (Keff + 7) >> 3;
#pragma unroll
    for (int s = 0; s < NSTG - 1; s++) {
        if (s < nk) { issueA(s * 8, s); issueB(s * 8, s); }
        CP_COMMIT();
    }

    for (int kt = 0; kt < nk; kt++) {
        int stg = kt % NSTG;
        asm volatile("cp.async.wait_group %0;\n" :: "n"(NSTG - 2));
        __syncthreads();

        const float* Ab = smemA[stg];
        const float* Bb = smemB[stg];
        unsigned af[4][4], bf[4][2];
        if (aK) {
#pragma unroll
            for (int mf = 0; mf < 4; mf++) {
                int cm = wm * 64 + mf * 16 + lq;
                af[mf][0] = f2tf(Ab[cm * 12 + lr]);
                af[mf][1] = f2tf(Ab[(cm + 8) * 12 + lr]);
                af[mf][2] = f2tf(Ab[cm * 12 + lr + 4]);
                af[mf][3] = f2tf(Ab[(cm + 8) * 12 + lr + 4]);
            }
        } else {
#pragma unroll
            for (int mf = 0; mf < 4; mf++) {
                int cm = wm * 64 + mf * 16 + lq;
                af[mf][0] = f2tf(Ab[lr * 132 + cm]);
                af[mf][1] = f2tf(Ab[lr * 132 + cm + 8]);
                af[mf][2] = f2tf(Ab[(lr + 4) * 132 + cm]);
                af[mf][3] = f2tf(Ab[(lr + 4) * 132 + cm + 8]);
            }
        }
        if (bN) {
#pragma unroll
            for (int nf = 0; nf < 4; nf++) {
                int cn = wn * 32 + nf * 8 + lq;
                bf[nf][0] = f2tf(Bb[lr * 132 + cn]);
                bf[nf][1] = f2tf(Bb[(lr + 4) * 132 + cn]);
            }
        } else {
#pragma unroll
            for (int nf = 0; nf < 4; nf++) {
                int cn = wn * 32 + nf * 8 + lq;
                bf[nf][0] = f2tf(Bb[cn * 12 + lr]);
                bf[nf][1] = f2tf(Bb[cn * 12 + lr + 4]);
            }
        }
#pragma unroll
        for (int mf = 0; mf < 4; mf++)
#pragma unroll
            for (int nf = 0; nf < 4; nf++)
                mma_tf32(acc[mf][nf], af[mf], bf[nf]);

        __syncthreads();
        int nxt = kt + NSTG - 1;
        if (nxt < nk) { issueA(nxt * 8, nxt % NSTG); issueB(nxt * 8, nxt % NSTG); }
        CP_COMMIT();
    }

    long long offO = (long long)bo * p.bO + (long long)bi * p.bO2;
    long long offBias = p.bBias * bz;
#pragma unroll
    for (int mf = 0; mf < 4; mf++) {
        int row = m0 + wm * 64 + mf * 16 + lq;
#pragma unroll
        for (int nf = 0; nf < 4; nf++) {
            int col = n0 + wn * 32 + nf * 8 + lr * 2;
            epi_write(p, row,     col,     acc[mf][nf][0], offO, offBias);
            epi_write(p, row,     col + 1, acc[mf][nf][1], offO, offBias);
            epi_write(p, row + 8, col,     acc[mf][nf][2], offO, offBias);
            epi_write(p, row + 8, col + 1, acc[mf][nf][3], offO, offBias);
        }
    }
}

// ---------------- elementwise / reduction kernels ----------------
__global__ void pool_k(const float* mem, float* pool) {
    int i = blockIdx.x * 256 + threadIdx.x;
    if (i >= Bn * Mn * Cn) return;
    int c = i % Cn;
    int r = i / Cn;
    int m = r % Mn;
    int b = r / Mn;
    const float* pp = mem + ((long long)b * Tn + m * (Tn / Mn)) * Cn + c;
    float s = 0.f;
#pragma unroll 8
    for (int j = 0; j < Tn / Mn; j++) s += pp[(long long)j * Cn];
    pool[i] = s * (1.f / (Tn / Mn));
}

__global__ void build_xa_k(const float* retr, const float* persist, const float* x, float* xa) {
    long long i = (long long)blockIdx.x * 256 + threadIdx.x;
    if (i >= (long long)Bn * TAn * Cn) return;
    int c = (int)(i % Cn);
    long long r = i / Cn;
    int t = (int)(r % TAn);
    int b = (int)(r / TAn);
    float v;
    if (t < Mn)        v = retr[((long long)b * Mn + t) * Cn + c];
    else if (t < PREn) v = persist[(long long)(t - Mn) * Cn + c];
    else               v = x[((long long)b * Tn + (t - PREn)) * Cn + c];
    xa[i] = v;
}

__global__ void ln_k(const float* x, float* o, const float* w, const float* bb) {
    long long row = blockIdx.x;
    const float* xr = x + row * Cn;
    float* orow = o + row * Cn;
    int t = threadIdx.x;
    __shared__ float s1[256], s2[256];
    float v0 = xr[t], v1 = xr[t + 256], v2 = xr[t + 512];
    s1[t] = v0 + v1 + v2;
    s2[t] = v0 * v0 + v1 * v1 + v2 * v2;
    __syncthreads();
    for (int st = 128; st > 0; st >>= 1) {
        if (t < st) { s1[t] += s1[t + st]; s2[t] += s2[t + st]; }
        __syncthreads();
    }
    float mean = s1[0] * (1.f / Cn);
    float var  = s2[0] * (1.f / Cn) - mean * mean;
    float rs = rsqrtf(var + 1e-5f);
    orow[t]       = (v0 - mean) * rs * w[t]       + bb[t];
    orow[t + 256] = (v1 - mean) * rs * w[t + 256] + bb[t + 256];
    orow[t + 512] = (v2 - mean) * rs * w[t + 512] + bb[t + 512];
}

// softmax over the causally-valid prefix of each row; zero-fill to the
// y-GEMM k-cap boundary so capped k-loops read exact zeros.
__global__ void softmax_k(float* a) {
    long long row = blockIdx.x;
    int m = (int)(row % TAn);
    float* r = a + row * TAn;
    int lim = (m < PREn) ? TAn : (m + 1);
    int end = (m < 128) ? TAn : (((m >> 7) + 1) << 7);
    if (end > TAn) end = TAn;
    int t = threadIdx.x;
    __shared__ float red[256];
    float mx = -1e30f;
    for (int c = t; c < lim; c += 256) mx = fmaxf(mx, r[c]);
    red[t] = mx; __syncthreads();
    for (int st = 128; st > 0; st >>= 1) { if (t < st) red[t] = fmaxf(red[t], red[t + st]); __syncthreads(); }
    mx = red[0]; __syncthreads();
    float s = 0.f;
    for (int c = t; c < lim; c += 256) { float e = __expf(r[c] - mx); r[c] = e; s += e; }
    red[t] = s; __syncthreads();
    for (int st = 128; st > 0; st >>= 1) { if (t < st) red[t] += red[t + st]; __syncthreads(); }
    float inv = 1.f / red[0];
    for (int c = t; c < lim; c += 256) r[c] *= inv;
    for (int c = lim + t; c < end; c += 256) r[c] = 0.f;
}

__global__ void copyout_k(const float* xa, float* go, float* dout) {
    long long i = (long long)blockIdx.x * 256 + threadIdx.x;
    if (i >= (long long)Bn * Tn * Cn) return;
    int c = (int)(i % Cn);
    long long r = i / Cn;
    int t = (int)(r % Tn);
    int b = (int)(r / Tn);
    float v = xa[((long long)b * TAn + PREn + t) * Cn + c];
    go[i] = v;
    dout[i] = v;
}

__global__ void colsum_part_k(const float* src, float* part, int cols) {
    int i = blockIdx.x * 256 + threadIdx.x;
    int total = SLICES * Bn * cols;
    if (i >= total) return;
    int s = i / (Bn * cols);
    int rem = i % (Bn * cols);
    int b = rem / cols, c = rem % cols;
    const float* p = src + ((long long)b * Tn + s * (Tn / SLICES)) * cols + c;
    float g = 0.f;
    for (int r = 0; r < Tn / SLICES; r++) g += p[(long long)r * cols];
    part[i] = g;
}

__global__ void colsum_fin_k(const float* part, const float* memb, const float* mom,
                             float* nb, float* nm, int n) {
    int i = blockIdx.x * 256 + threadIdx.x;
    if (i >= n) return;
    float g = 0.f;
    for (int s = 0; s < SLICES; s++) g += part[(long long)s * n + i];
    float m2 = 0.9f * mom[i] + g;
    nm[i] = m2;
    nb[i] = 0.999f * memb[i] - 0.01f * m2;
}

// ---------------- host ----------------
static void run_gemm(const float* A, long long sAm, long long sAk, long long bA, long long bA2,
                     const float* Bm, long long sBk, long long sBn, long long bB, long long bB2,
                     float* O, long long sOm, long long sOn, long long bO, long long bO2,
                     int M, int N, int K, int batch, int binner,
                     const float* bias, long long bBias, int mode,
                     float* O2, const float* aux, const float* aux2, float scale, int tri = 0)
{
    GP p;
    p.A = A; p.Bm = Bm; p.O = O; p.O2 = O2; p.bias = bias; p.aux = aux; p.aux2 = aux2;
    p.M = M; p.N = N; p.K = K; p.binner = binner;
    p.sAm = sAm; p.sAk = sAk; p.bA = bA; p.bA2 = bA2;
    p.sBk = sBk; p.sBn = sBn; p.bB = bB; p.bB2 = bB2;
    p.sOm = sOm; p.sOn = sOn; p.bO = bO; p.bO2 = bO2;
    p.bBias = bBias; p.mode = mode; p.prefix = PREn; p.tri = tri; p.scale = scale;
    dim3 g((N + 127) / 128, (M + 127) / 128, batch);
    gemm_tc<<<g, 256>>>(p);
}

extern "C" void kernel_launch(void* const* d_in, const int* in_sizes, int n_in,
                              void* d_out, int out_size) {
    const float* x           = (const float*)d_in[0];
    const float* persist     = (const float*)d_in[1];
    const float* ln1_w       = (const float*)d_in[2];
    const float* ln1_b       = (const float*)d_in[3];
    const float* ln2_w       = (const float*)d_in[4];
    const float* ln2_b       = (const float*)d_in[5];
    const float* attn_w      = (const float*)d_in[6];
    const float* attn_b      = (const float*)d_in[7];
    const float* attn_proj_w = (const float*)d_in[8];
    const float* attn_proj_b = (const float*)d_in[9];
    const float* fc_w        = (const float*)d_in[10];
    const float* fc_b        = (const float*)d_in[11];
    const float* mlp_proj_w  = (const float*)d_in[12];
    const float* mlp_proj_b  = (const float*)d_in[13];
    const float* q_w         = (const float*)d_in[14];
    const float* q_b         = (const float*)d_in[15];
    const float* k_w         = (const float*)d_in[16];
    const float* k_b         = (const float*)d_in[17];
    const float* v_w         = (const float*)d_in[18];
    const float* v_b         = (const float*)d_in[19];
    const float* o_w         = (const float*)d_in[20];
    const float* o_b         = (const float*)d_in[21];
    const float* mem_w0      = (const float*)d_in[22];
    const float* mem_b0      = (const float*)d_in[23];
    const float* mem_w1      = (const float*)d_in[24];
    const float* mem_b1      = (const float*)d_in[25];
    const float* mom_w0      = (const float*)d_in[26];
    const float* mom_b0      = (const float*)d_in[27];
    const float* mom_w1      = (const float*)d_in[28];
    const float* mom_b1      = (const float*)d_in[29];
    float* out = (float*)d_out;

    float *Q, *HB, *MEM, *POOL, *RETR, *XA, *HLN, *QKV, *ATT, *Y, *FC, *OUT, *KEY, *VAL,
          *PRE, *HH, *DPR, *DHH, *P0, *P1;
    cudaGetSymbolAddress((void**)&Q, g_q);
    cudaGetSymbolAddress((void**)&HB, g_hbuf);
    cudaGetSymbolAddress((void**)&MEM, g_mem);
    cudaGetSymbolAddress((void**)&POOL, g_pool);
    cudaGetSymbolAddress((void**)&RETR, g_retr);
    cudaGetSymbolAddress((void**)&XA, g_xa);
    cudaGetSymbolAddress((void**)&HLN, g_hln);
    cudaGetSymbolAddress((void**)&QKV, g_qkv);
    cudaGetSymbolAddress((void**)&ATT, g_att);
    cudaGetSymbolAddress((void**)&Y, g_y);
    cudaGetSymbolAddress((void**)&FC, g_fc);
    cudaGetSymbolAddress((void**)&OUT, g_o);
    cudaGetSymbolAddress((void**)&KEY, g_key);
    cudaGetSymbolAddress((void**)&VAL, g_val);
    cudaGetSymbolAddress((void**)&PRE, g_pre);
    cudaGetSymbolAddress((void**)&HH, g_hh);
    cudaGetSymbolAddress((void**)&DPR, g_dpr);
    cudaGetSymbolAddress((void**)&DHH, g_dhh);
    cudaGetSymbolAddress((void**)&P0, g_p0);
    cudaGetSymbolAddress((void**)&P1, g_p1);

    const long long TC   = (long long)Tn * Cn;
    const long long TH   = (long long)Tn * HIDn;
    const long long CH   = (long long)Cn * HIDn;
    const long long HC   = (long long)HIDn * Cn;
    const long long TAC  = (long long)TAn * Cn;
    const long long TA3C = (long long)TAn * 3 * Cn;
    const long long TATA = (long long)TAn * TAn;

    const long long o_nw0  = 6291456LL;
    const long long o_nb0  = 15728640LL;
    const long long o_nw1  = 15740928LL;
    const long long o_nb1  = 25178112LL;
    const long long o_nmw0 = 25184256LL;
    const long long o_nmb0 = 34621440LL;
    const long long o_nmw1 = 34633728LL;
    const long long o_nmb1 = 44070912LL;

    run_gemm(x, Cn, 1, 0, 0,  q_w, 1, Cn, 0, 0,  Q, Cn, 1, 0, 0,
             Bn * Tn, Cn, Cn, 1, 1, q_b, 0, 0, nullptr, nullptr, nullptr, 0.f);
    run_gemm(Q, Cn, 1, TC, 0,  mem_w0, 1, Cn, HC, 0,  HB, HIDn, 1, TH, 0,
             Tn, HIDn, Cn, Bn, 1, mem_b0, HIDn, 1, nullptr, nullptr, nullptr, 0.f);
    run_gemm(HB, HIDn, 1, TH, 0,  mem_w1, 1, HIDn, CH, 0,  MEM, Cn, 1, TC, 0,
             Tn, Cn, HIDn, Bn, 1, mem_b1, Cn, 0, nullptr, nullptr, nullptr, 0.f);
    pool_k<<<(Bn * Mn * Cn + 255) / 256, 256>>>(MEM, POOL);
    run_gemm(POOL, Cn, 1, 0, 0,  o_w, 1, Cn, 0, 0,  RETR, Cn, 1, 0, 0,
             Bn * Mn, Cn, Cn, 1, 1, o_b, 0, 0, nullptr, nullptr, nullptr, 0.f);
    build_xa_k<<<(int)(((long long)Bn * TAn * Cn + 255) / 256), 256>>>(RETR, persist, x, XA);
    ln_k<<<Bn * TAn, 256>>>(XA, HLN, ln1_w, ln1_b);
    run_gemm(HLN, Cn, 1, 0, 0,  attn_w, 1, Cn, 0, 0,  QKV, 3 * Cn, 1, 0, 0,
             Bn * TAn, 3 * Cn, Cn, 1, 1, attn_b, 0, 0, nullptr, nullptr, nullptr, 0.f);
    // scores = scale * Q K^T with prefix-causal mask; skip fully-masked blocks
    run_gemm(QKV, 3 * Cn, 1, TA3C, 64,  QKV + Cn, 1, 3 * Cn, TA3C, 64,
             ATT, TAn, 1, (long long)Hn * TATA, TATA,
             TAn, TAn, 64, Bn * Hn, Hn, nullptr, 0, 3, nullptr, nullptr, nullptr, 0.125f, 1);
    softmax_k<<<Bn * Hn * TAn, 256>>>(ATT);
    // y = att @ V with per-block K cap
    run_gemm(ATT, TAn, 1, (long long)Hn * TATA, TATA,  QKV + 2 * Cn, 3 * Cn, 1, TA3C, 64,
             Y, Cn, 1, TAC, 64,
             TAn, 64, TAn, Bn * Hn, Hn, nullptr, 0, 0, nullptr, nullptr, nullptr, 0.f, 2);
    run_gemm(Y, Cn, 1, 0, 0,  attn_proj_w, 1, Cn, 0, 0,  XA, Cn, 1, 0, 0,
             Bn * TAn, Cn, Cn, 1, 1, attn_proj_b, 0, 4, nullptr, XA, nullptr, 0.f);
    ln_k<<<Bn * TAn, 256>>>(XA, HLN, ln2_w, ln2_b);
    run_gemm(HLN, Cn, 1, 0, 0,  fc_w, 1, Cn, 0, 0,  FC, 4 * Cn, 1, 0, 0,
             Bn * TAn, 4 * Cn, Cn, 1, 1, fc_b, 0, 2, nullptr, nullptr, nullptr, 0.f);
    run_gemm(FC, 4 * Cn, 1, 0, 0,  mlp_proj_w, 1, 4 * Cn, 0, 0,  XA, Cn, 1, 0, 0,
             Bn * TAn, Cn, 4 * Cn, 1, 1, mlp_proj_b, 0, 4, nullptr, XA, nullptr, 0.f);
    copyout_k<<<(int)(((long long)Bn * Tn * Cn + 255) / 256), 256>>>(XA, OUT, out);
    run_gemm(OUT, Cn, 1, 0, 0,  k_w, 1, Cn, 0, 0,  KEY, Cn, 1, 0, 0,
             Bn * Tn, Cn, Cn, 1, 1, k_b, 0, 0, nullptr, nullptr, nullptr, 0.f);
    run_gemm(OUT, Cn, 1, 0, 0,  v_w, 1, Cn, 0, 0,  VAL, Cn, 1, 0, 0,
             Bn * Tn, Cn, Cn, 1, 1, v_b, 0, 0, nullptr, nullptr, nullptr, 0.f);
    run_gemm(KEY, Cn, 1, TC, 0,  mem_w0, 1, Cn, HC, 0,  HH, HIDn, 1, TH, 0,
             Tn, HIDn, Cn, Bn, 1, mem_b0, HIDn, 1, PRE, nullptr, nullptr, 0.f);
    run_gemm(HH, HIDn, 1, TH, 0,  mem_w1, 1, HIDn, CH, 0,  DPR, Cn, 1, TC, 0,
             Tn, Cn, HIDn, Bn, 1, mem_b1, Cn, 5, nullptr, VAL, nullptr,
             2.f / (float)(Tn * Cn));
    run_gemm(DPR, 1, Cn, TC, 0,  HH, HIDn, 1, TH, 0,  out + o_nw1, HIDn, 1, CH, 0,
             Cn, HIDn, Tn, Bn, 1, nullptr, 0, 7, out + o_nmw1, mem_w1, mom_w1, 0.f);
    run_gemm(DPR, Cn, 1, TC, 0,  mem_w1, HIDn, 1, CH, 0,  DHH, HIDn, 1, TH, 0,
             Tn, HIDn, Cn, Bn, 1, nullptr, 0, 6, nullptr, PRE, nullptr, 0.f);
    run_gemm(DHH, 1, HIDn, TH, 0,  KEY, Cn, 1, TC, 0,  out + o_nw0, Cn, 1, HC, 0,
             HIDn, Cn, Tn, Bn, 1, nullptr, 0, 7, out + o_nmw0, mem_w0, mom_w0, 0.f);
    colsum_part_k<<<(SLICES * Bn * Cn + 255) / 256, 256>>>(DPR, P1, Cn);
    colsum_fin_k<<<(Bn * Cn + 255) / 256, 256>>>(P1, mem_b1, mom_b1,
                                                 out + o_nb1, out + o_nmb1, Bn * Cn);
    colsum_part_k<<<(SLICES * Bn * HIDn + 255) / 256, 256>>>(DHH, P0, HIDn);
    colsum_fin_k<<<(Bn * HIDn + 255) / 256, 256>>>(P0, mem_b0, mom_b0,
                                                   out + o_nb0, out + o_nmb0, Bn * HIDn);
    (void)in_sizes; (void)n_in; (void)out_size;
}

// round 11
// speedup vs baseline: 1.6571x; 1.6571x over previous
#include <cuda_runtime.h>

#define Bn   8
#define Tn   1024
#define Cn   768
#define Hn   12
#define HIDn 1536
#define Mn   16
#define Pn   4
#define PREn 20
#define TAn  1044
#define SLICES 16

// ---------------- scratch (device globals; no cudaMalloc allowed) ----------------
__device__ float g_q   [Bn*Tn*Cn];
__device__ float g_hbuf[Bn*Tn*HIDn];
__device__ float g_mem [Bn*Tn*Cn];
__device__ float g_pool[Bn*Mn*Cn];
__device__ float g_retr[Bn*Mn*Cn];
__device__ float g_xa  [Bn*TAn*Cn];
__device__ float g_hln [Bn*TAn*Cn];
__device__ float g_qkv [Bn*TAn*3*Cn];
__device__ float g_att [Bn*Hn*TAn*TAn];   // ~418MB
__device__ float g_y   [Bn*TAn*Cn];
__device__ float g_fc  [Bn*TAn*4*Cn];
__device__ float g_o   [Bn*Tn*Cn];
__device__ float g_key [Bn*Tn*Cn];
__device__ float g_val [Bn*Tn*Cn];
__device__ float g_pre [Bn*Tn*HIDn];
__device__ float g_hh  [Bn*Tn*HIDn];
__device__ float g_dpr [Bn*Tn*Cn];
__device__ float g_dhh [Bn*Tn*HIDn];
__device__ float g_p0  [SLICES*Bn*HIDn];
__device__ float g_p1  [SLICES*Bn*Cn];

// ---------------- generic strided batched GEMM params ----------------
struct GP {
    const float* A; const float* Bm; float* O; float* O2;
    const float* bias; const float* aux; const float* aux2;
    int M, N, K, binner;
    long long sAm, sAk, bA, bA2;
    long long sBk, sBn, bB, bB2;
    long long sOm, sOn, bO, bO2;
    long long bBias;
    int mode, prefix, tri;
    float scale;
};
// modes: 0=bias 1=silu(+pre->O2) 2=gelu 3=attn scale+mask 4=residual-add
//        5=dpred 6=silu-bwd(aux=pre) 7=momentum update (aux=mem, aux2=mom, O=nw, O2=nmom)
// tri: 1=skip fully-masked blocks (scores), 2=cap K at m0+128 (attn y)

__device__ __forceinline__ unsigned f2tf(float x) {
    unsigned r;
    asm("cvt.rna.tf32.f32 %0, %1;" : "=r"(r) : "f"(x));
    return r;
}

__device__ __forceinline__ void mma_tf32(float* c, const unsigned* a, const unsigned* b) {
    asm volatile(
        "mma.sync.aligned.m16n8k8.row.col.f32.tf32.tf32.f32 "
        "{%0,%1,%2,%3}, {%4,%5,%6,%7}, {%8,%9}, {%0,%1,%2,%3};\n"
        : "+f"(c[0]), "+f"(c[1]), "+f"(c[2]), "+f"(c[3])
        : "r"(a[0]), "r"(a[1]), "r"(a[2]), "r"(a[3]), "r"(b[0]), "r"(b[1]));
}

__device__ __forceinline__ void cp16(float* dst, const float* src, bool pred) {
    unsigned d = (unsigned)__cvta_generic_to_shared(dst);
    int sz = pred ? 16 : 0;
    asm volatile("cp.async.cg.shared.global [%0], [%1], 16, %2;\n"
                 :: "r"(d), "l"(src), "r"(sz));
}
#define CP_COMMIT() asm volatile("cp.async.commit_group;\n" ::)

__device__ __forceinline__ void epi_write(const GP& p, int m, int n, float v,
                                          long long offO, long long offBias) {
    if (m >= p.M || n >= p.N) return;
    long long o = offO + (long long)m * p.sOm + (long long)n * p.sOn;
    float bsv = p.bias ? p.bias[offBias + n] : 0.f;
    switch (p.mode) {
        case 0: p.O[o] = v + bsv; break;
        case 1: { float z = v + bsv; if (p.O2) p.O2[o] = z;
                  float sg = 1.f / (1.f + __expf(-z)); p.O[o] = z * sg; } break;
        case 2: { float z = v + bsv; p.O[o] = 0.5f * z * (1.f + erff(z * 0.70710678118f)); } break;
        case 3: { float z = v * p.scale; if (m >= p.prefix && n > m) z = -1e30f; p.O[o] = z; } break;
        case 4: p.O[o] = p.aux[o] + v + bsv; break;
        case 5: p.O[o] = (v + bsv - p.aux[o]) * p.scale; break;
        case 6: { float z = p.aux[o]; float sg = 1.f / (1.f + __expf(-z));
                  p.O[o] = v * sg * (1.f + z * (1.f - sg)); } break;
        case 7: { float nm = 0.9f * p.aux2[o] + v; p.O2[o] = nm;
                  p.O[o] = 0.999f * p.aux[o] - 0.01f * nm; } break;
    }
}

// ---- tf32 tensor-core GEMM: 128x128 block, k-tile 16, 8 warps ----
// cp.async GMEM->SMEM (no register staging), 2-stage, ONE sync per k-iter,
// 32 MMAs per iter. Orientation-matched smem layouts, conflict-free frag LDS:
//   k-contiguous operand : row layout [128][20]
//   m/n-contiguous       : col layout [16][132]
__global__ void __launch_bounds__(256, 2) gemm_tc(GP p) {
    __shared__ float sA[2][2560];
    __shared__ float sB[2][2560];
    int bz = blockIdx.z;
    int bo = bz / p.binner, bi = bz % p.binner;
    const float* Ap = p.A  + (long long)bo * p.bA + (long long)bi * p.bA2;
    const float* Bp = p.Bm + (long long)bo * p.bB + (long long)bi * p.bB2;
    int m0 = blockIdx.y * 128, n0 = blockIdx.x * 128;

    // triangular-mask shortcuts
    if (p.tri == 1 && m0 > 0 && n0 >= m0 + 128) return;
    int Keff = p.K;
    if (p.tri == 2 && m0 > 0 && m0 + 128 < Keff) Keff = m0 + 128;

    int tid = threadIdx.x;
    int warp = tid >> 5, lane = tid & 31;
    int wm = warp & 1, wn = warp >> 1;      // warp tile: 64 (m) x 32 (n)
    int lq = lane >> 2, lr = lane & 3;

    float acc[4][4][4];
#pragma unroll
    for (int i = 0; i < 4; i++)
#pragma unroll
        for (int j = 0; j < 4; j++)
#pragma unroll
            for (int r = 0; r < 4; r++) acc[i][j][r] = 0.f;

    const bool aK = (p.sAk == 1);     // A contiguous along k
    const bool bN = (p.sBn == 1);     // B contiguous along n

    // All M/N/K dims used are divisible by 4, so a 16B cp covers in-bounds data
    // whenever its first element is in bounds.
    auto issueA = [&](int k0, int stg) {
        float* dst = sA[stg];
#pragma unroll
        for (int i = 0; i < 2; i++) {
            int lin = tid + i * 256;
            if (aK) {                           // row layout [128][20]
                int row = lin >> 2, kv = (lin & 3) * 4;
                int gm = m0 + row, gk = k0 + kv;
                bool ok = (gm < p.M) && (gk < Keff);
                const float* src = ok ? (Ap + (long long)gm * p.sAm + gk) : Ap;
                cp16(&dst[row * 20 + kv], src, ok);
            } else {                            // col layout [16][132]
                int kr = lin >> 5, mv = (lin & 31) * 4;
                int gk = k0 + kr, gm = m0 + mv;
                bool ok = (gk < Keff) && (gm < p.M);
                const float* src = ok ? (Ap + (long long)gm + (long long)gk * p.sAk) : Ap;
                cp16(&dst[kr * 132 + mv], src, ok);
            }
        }
    };
    auto issueB = [&](int k0, int stg) {
        float* dst = sB[stg];
#pragma unroll
        for (int i = 0; i < 2; i++) {
            int lin = tid + i * 256;
            if (bN) {                           // col layout [16][132]
                int kr = lin >> 5, nv = (lin & 31) * 4;
                int gk = k0 + kr, gn = n0 + nv;
                bool ok = (gk < Keff) && (gn < p.N);
                const float* src = ok ? (Bp + (long long)gk * p.sBk + gn) : Bp;
                cp16(&dst[kr * 132 + nv], src, ok);
            } else {                            // row layout [128][20]
                int row = lin >> 2, kv = (lin & 3) * 4;
                int gn = n0 + row, gk = k0 + kv;
                bool ok = (gn < p.N) && (gk < Keff);
                const float* src = ok ? (Bp + (long long)gk * p.sBk + (long long)gn * p.sBn) : Bp;
                cp16(&dst[row * 20 + kv], src, ok);
            }
        }
    };

    int nk = (Keff + 15) >> 4;
    issueA(0, 0); issueB(0, 0);
    CP_COMMIT();

    for (int kt = 0; kt < nk; kt++) {
        int buf = kt & 1;
        asm volatile("cp.async.wait_group 0;\n" ::);
        __syncthreads();
        if (kt + 1 < nk) {
            issueA((kt + 1) << 4, buf ^ 1);
            issueB((kt + 1) << 4, buf ^ 1);
            CP_COMMIT();
        }

        const float* Ab = sA[buf];
        const float* Bb = sB[buf];
#pragma unroll
        for (int s = 0; s < 2; s++) {
            int k8 = s * 8;
            unsigned af[4][4], bf[4][2];
            if (aK) {
#pragma unroll
                for (int mf = 0; mf < 4; mf++) {
                    int cm = wm * 64 + mf * 16 + lq;
                    af[mf][0] = f2tf(Ab[cm * 20 + k8 + lr]);
                    af[mf][1] = f2tf(Ab[(cm + 8) * 20 + k8 + lr]);
                    af[mf][2] = f2tf(Ab[cm * 20 + k8 + lr + 4]);
                    af[mf][3] = f2tf(Ab[(cm + 8) * 20 + k8 + lr + 4]);
                }
            } else {
#pragma unroll
                for (int mf = 0; mf < 4; mf++) {
                    int cm = wm * 64 + mf * 16 + lq;
                    af[mf][0] = f2tf(Ab[(k8 + lr) * 132 + cm]);
                    af[mf][1] = f2tf(Ab[(k8 + lr) * 132 + cm + 8]);
                    af[mf][2] = f2tf(Ab[(k8 + lr + 4) * 132 + cm]);
                    af[mf][3] = f2tf(Ab[(k8 + lr + 4) * 132 + cm + 8]);
                }
            }
            if (bN) {
#pragma unroll
                for (int nf = 0; nf < 4; nf++) {
                    int cn = wn * 32 + nf * 8 + lq;
                    bf[nf][0] = f2tf(Bb[(k8 + lr) * 132 + cn]);
                    bf[nf][1] = f2tf(Bb[(k8 + lr + 4) * 132 + cn]);
                }
            } else {
#pragma unroll
                for (int nf = 0; nf < 4; nf++) {
                    int cn = wn * 32 + nf * 8 + lq;
                    bf[nf][0] = f2tf(Bb[cn * 20 + k8 + lr]);
                    bf[nf][1] = f2tf(Bb[cn * 20 + k8 + lr + 4]);
                }
            }
#pragma unroll
            for (int mf = 0; mf < 4; mf++)
#pragma unroll
                for (int nf = 0; nf < 4; nf++)
                    mma_tf32(acc[mf][nf], af[mf], bf[nf]);
        }
    }

    long long offO = (long long)bo * p.bO + (long long)bi * p.bO2;
    long long offBias = p.bBias * bz;
#pragma unroll
    for (int mf = 0; mf < 4; mf++) {
        int row = m0 + wm * 64 + mf * 16 + lq;
#pragma unroll
        for (int nf = 0; nf < 4; nf++) {
            int col = n0 + wn * 32 + nf * 8 + lr * 2;
            epi_write(p, row,     col,     acc[mf][nf][0], offO, offBias);
            epi_write(p, row,     col + 1, acc[mf][nf][1], offO, offBias);
            epi_write(p, row + 8, col,     acc[mf][nf][2], offO, offBias);
            epi_write(p, row + 8, col + 1, acc[mf][nf][3], offO, offBias);
        }
    }
}

// ---------------- elementwise / reduction kernels ----------------
__global__ void pool_k(const float* mem, float* pool) {
    int i = blockIdx.x * 256 + threadIdx.x;
    if (i >= Bn * Mn * Cn) return;
    int c = i % Cn;
    int r = i / Cn;
    int m = r % Mn;
    int b = r / Mn;
    const float* pp = mem + ((long long)b * Tn + m * (Tn / Mn)) * Cn + c;
    float s = 0.f;
#pragma unroll 8
    for (int j = 0; j < Tn / Mn; j++) s += pp[(long long)j * Cn];
    pool[i] = s * (1.f / (Tn / Mn));
}

__global__ void build_xa_k(const float* retr, const float* persist, const float* x, float* xa) {
    long long i = (long long)blockIdx.x * 256 + threadIdx.x;
    if (i >= (long long)Bn * TAn * Cn) return;
    int c = (int)(i % Cn);
    long long r = i / Cn;
    int t = (int)(r % TAn);
    int b = (int)(r / TAn);
    float v;
    if (t < Mn)        v = retr[((long long)b * Mn + t) * Cn + c];
    else if (t < PREn) v = persist[(long long)(t - Mn) * Cn + c];
    else               v = x[((long long)b * Tn + (t - PREn)) * Cn + c];
    xa[i] = v;
}

__global__ void ln_k(const float* x, float* o, const float* w, const float* bb) {
    long long row = blockIdx.x;
    const float* xr = x + row * Cn;
    float* orow = o + row * Cn;
    int t = threadIdx.x;
    __shared__ float s1[256], s2[256];
    float v0 = xr[t], v1 = xr[t + 256], v2 = xr[t + 512];
    s1[t] = v0 + v1 + v2;
    s2[t] = v0 * v0 + v1 * v1 + v2 * v2;
    __syncthreads();
    for (int st = 128; st > 0; st >>= 1) {
        if (t < st) { s1[t] += s1[t + st]; s2[t] += s2[t + st]; }
        __syncthreads();
    }
    float mean = s1[0] * (1.f / Cn);
    float var  = s2[0] * (1.f / Cn) - mean * mean;
    float rs = rsqrtf(var + 1e-5f);
    orow[t]       = (v0 - mean) * rs * w[t]       + bb[t];
    orow[t + 256] = (v1 - mean) * rs * w[t + 256] + bb[t + 256];
    orow[t + 512] = (v2 - mean) * rs * w[t + 512] + bb[t + 512];
}

// softmax over the causally-valid prefix of each row; zero-fill to the
// y-GEMM k-cap boundary so capped k-loops read exact zeros.
__global__ void softmax_k(float* a) {
    long long row = blockIdx.x;
    int m = (int)(row % TAn);
    float* r = a + row * TAn;
    int lim = (m < PREn) ? TAn : (m + 1);
    int end = (m < 128) ? TAn : (((m >> 7) + 1) << 7);
    if (end > TAn) end = TAn;
    int t = threadIdx.x;
    __shared__ float red[256];
    float mx = -1e30f;
    for (int c = t; c < lim; c += 256) mx = fmaxf(mx, r[c]);
    red[t] = mx; __syncthreads();
    for (int st = 128; st > 0; st >>= 1) { if (t < st) red[t] = fmaxf(red[t], red[t + st]); __syncthreads(); }
    mx = red[0]; __syncthreads();
    float s = 0.f;
    for (int c = t; c < lim; c += 256) { float e = __expf(r[c] - mx); r[c] = e; s += e; }
    red[t] = s; __syncthreads();
    for (int st = 128; st > 0; st >>= 1) { if (t < st) red[t] += red[t + st]; __syncthreads(); }
    float inv = 1.f / red[0];
    for (int c = t; c < lim; c += 256) r[c] *= inv;
    for (int c = lim + t; c < end; c += 256) r[c] = 0.f;
}

__global__ void copyout_k(const float* xa, float* go, float* dout) {
    long long i = (long long)blockIdx.x * 256 + threadIdx.x;
    if (i >= (long long)Bn * Tn * Cn) return;
    int c = (int)(i % Cn);
    long long r = i / Cn;
    int t = (int)(r % Tn);
    int b = (int)(r / Tn);
    float v = xa[((long long)b * TAn + PREn + t) * Cn + c];
    go[i] = v;
    dout[i] = v;
}

__global__ void colsum_part_k(const float* src, float* part, int cols) {
    int i = blockIdx.x * 256 + threadIdx.x;
    int total = SLICES * Bn * cols;
    if (i >= total) return;
    int s = i / (Bn * cols);
    int rem = i % (Bn * cols);
    int b = rem / cols, c = rem % cols;
    const float* p = src + ((long long)b * Tn + s * (Tn / SLICES)) * cols + c;
    float g = 0.f;
    for (int r = 0; r < Tn / SLICES; r++) g += p[(long long)r * cols];
    part[i] = g;
}

__global__ void colsum_fin_k(const float* part, const float* memb, const float* mom,
                             float* nb, float* nm, int n) {
    int i = blockIdx.x * 256 + threadIdx.x;
    if (i >= n) return;
    float g = 0.f;
    for (int s = 0; s < SLICES; s++) g += part[(long long)s * n + i];
    float m2 = 0.9f * mom[i] + g;
    nm[i] = m2;
    nb[i] = 0.999f * memb[i] - 0.01f * m2;
}

// ---------------- host ----------------
static void run_gemm(const float* A, long long sAm, long long sAk, long long bA, long long bA2,
                     const float* Bm, long long sBk, long long sBn, long long bB, long long bB2,
                     float* O, long long sOm, long long sOn, long long bO, long long bO2,
                     int M, int N, int K, int batch, int binner,
                     const float* bias, long long bBias, int mode,
                     float* O2, const float* aux, const float* aux2, float scale, int tri = 0)
{
    GP p;
    p.A = A; p.Bm = Bm; p.O = O; p.O2 = O2; p.bias = bias; p.aux = aux; p.aux2 = aux2;
    p.M = M; p.N = N; p.K = K; p.binner = binner;
    p.sAm = sAm; p.sAk = sAk; p.bA = bA; p.bA2 = bA2;
    p.sBk = sBk; p.sBn = sBn; p.bB = bB; p.bB2 = bB2;
    p.sOm = sOm; p.sOn = sOn; p.bO = bO; p.bO2 = bO2;
    p.bBias = bBias; p.mode = mode; p.prefix = PREn; p.tri = tri; p.scale = scale;
    dim3 g((N + 127) / 128, (M + 127) / 128, batch);
    gemm_tc<<<g, 256>>>(p);
}

extern "C" void kernel_launch(void* const* d_in, const int* in_sizes, int n_in,
                              void* d_out, int out_size) {
    const float* x           = (const float*)d_in[0];
    const float* persist     = (const float*)d_in[1];
    const float* ln1_w       = (const float*)d_in[2];
    const float* ln1_b       = (const float*)d_in[3];
    const float* ln2_w       = (const float*)d_in[4];
    const float* ln2_b       = (const float*)d_in[5];
    const float* attn_w      = (const float*)d_in[6];
    const float* attn_b      = (const float*)d_in[7];
    const float* attn_proj_w = (const float*)d_in[8];
    const float* attn_proj_b = (const float*)d_in[9];
    const float* fc_w        = (const float*)d_in[10];
    const float* fc_b        = (const float*)d_in[11];
    const float* mlp_proj_w  = (const float*)d_in[12];
    const float* mlp_proj_b  = (const float*)d_in[13];
    const float* q_w         = (const float*)d_in[14];
    const float* q_b         = (const float*)d_in[15];
    const float* k_w         = (const float*)d_in[16];
    const float* k_b         = (const float*)d_in[17];
    const float* v_w         = (const float*)d_in[18];
    const float* v_b         = (const float*)d_in[19];
    const float* o_w         = (const float*)d_in[20];
    const float* o_b         = (const float*)d_in[21];
    const float* mem_w0      = (const float*)d_in[22];
    const float* mem_b0      = (const float*)d_in[23];
    const float* mem_w1      = (const float*)d_in[24];
    const float* mem_b1      = (const float*)d_in[25];
    const float* mom_w0      = (const float*)d_in[26];
    const float* mom_b0      = (const float*)d_in[27];
    const float* mom_w1      = (const float*)d_in[28];
    const float* mom_b1      = (const float*)d_in[29];
    float* out = (float*)d_out;

    float *Q, *HB, *MEM, *POOL, *RETR, *XA, *HLN, *QKV, *ATT, *Y, *FC, *OUT, *KEY, *VAL,
          *PRE, *HH, *DPR, *DHH, *P0, *P1;
    cudaGetSymbolAddress((void**)&Q, g_q);
    cudaGetSymbolAddress((void**)&HB, g_hbuf);
    cudaGetSymbolAddress((void**)&MEM, g_mem);
    cudaGetSymbolAddress((void**)&POOL, g_pool);
    cudaGetSymbolAddress((void**)&RETR, g_retr);
    cudaGetSymbolAddress((void**)&XA, g_xa);
    cudaGetSymbolAddress((void**)&HLN, g_hln);
    cudaGetSymbolAddress((void**)&QKV, g_qkv);
    cudaGetSymbolAddress((void**)&ATT, g_att);
    cudaGetSymbolAddress((void**)&Y, g_y);
    cudaGetSymbolAddress((void**)&FC, g_fc);
    cudaGetSymbolAddress((void**)&OUT, g_o);
    cudaGetSymbolAddress((void**)&KEY, g_key);
    cudaGetSymbolAddress((void**)&VAL, g_val);
    cudaGetSymbolAddress((void**)&PRE, g_pre);
    cudaGetSymbolAddress((void**)&HH, g_hh);
    cudaGetSymbolAddress((void**)&DPR, g_dpr);
    cudaGetSymbolAddress((void**)&DHH, g_dhh);
    cudaGetSymbolAddress((void**)&P0, g_p0);
    cudaGetSymbolAddress((void**)&P1, g_p1);

    const long long TC   = (long long)Tn * Cn;
    const long long TH   = (long long)Tn * HIDn;
    const long long CH   = (long long)Cn * HIDn;
    const long long HC   = (long long)HIDn * Cn;
    const long long TAC  = (long long)TAn * Cn;
    const long long TA3C = (long long)TAn * 3 * Cn;
    const long long TATA = (long long)TAn * TAn;

    const long long o_nw0  = 6291456LL;
    const long long o_nb0  = 15728640LL;
    const long long o_nw1  = 15740928LL;
    const long long o_nb1  = 25178112LL;
    const long long o_nmw0 = 25184256LL;
    const long long o_nmb0 = 34621440LL;
    const long long o_nmw1 = 34633728LL;
    const long long o_nmb1 = 44070912LL;

    run_gemm(x, Cn, 1, 0, 0,  q_w, 1, Cn, 0, 0,  Q, Cn, 1, 0, 0,
             Bn * Tn, Cn, Cn, 1, 1, q_b, 0, 0, nullptr, nullptr, nullptr, 0.f);
    run_gemm(Q, Cn, 1, TC, 0,  mem_w0, 1, Cn, HC, 0,  HB, HIDn, 1, TH, 0,
             Tn, HIDn, Cn, Bn, 1, mem_b0, HIDn, 1, nullptr, nullptr, nullptr, 0.f);
    run_gemm(HB, HIDn, 1, TH, 0,  mem_w1, 1, HIDn, CH, 0,  MEM, Cn, 1, TC, 0,
             Tn, Cn, HIDn, Bn, 1, mem_b1, Cn, 0, nullptr, nullptr, nullptr, 0.f);
    pool_k<<<(Bn * Mn * Cn + 255) / 256, 256>>>(MEM, POOL);
    run_gemm(POOL, Cn, 1, 0, 0,  o_w, 1, Cn, 0, 0,  RETR, Cn, 1, 0, 0,
             Bn * Mn, Cn, Cn, 1, 1, o_b, 0, 0, nullptr, nullptr, nullptr, 0.f);
    build_xa_k<<<(int)(((long long)Bn * TAn * Cn + 255) / 256), 256>>>(RETR, persist, x, XA);
    ln_k<<<Bn * TAn, 256>>>(XA, HLN, ln1_w, ln1_b);
    run_gemm(HLN, Cn, 1, 0, 0,  attn_w, 1, Cn, 0, 0,  QKV, 3 * Cn, 1, 0, 0,
             Bn * TAn, 3 * Cn, Cn, 1, 1, attn_b, 0, 0, nullptr, nullptr, nullptr, 0.f);
    // scores = scale * Q K^T with prefix-causal mask; skip fully-masked blocks
    run_gemm(QKV, 3 * Cn, 1, TA3C, 64,  QKV + Cn, 1, 3 * Cn, TA3C, 64,
             ATT, TAn, 1, (long long)Hn * TATA, TATA,
             TAn, TAn, 64, Bn * Hn, Hn, nullptr, 0, 3, nullptr, nullptr, nullptr, 0.125f, 1);
    softmax_k<<<Bn * Hn * TAn, 256>>>(ATT);
    // y = att @ V with per-block K cap
    run_gemm(ATT, TAn, 1, (long long)Hn * TATA, TATA,  QKV + 2 * Cn, 3 * Cn, 1, TA3C, 64,
             Y, Cn, 1, TAC, 64,
             TAn, 64, TAn, Bn * Hn, Hn, nullptr, 0, 0, nullptr, nullptr, nullptr, 0.f, 2);
    run_gemm(Y, Cn, 1, 0, 0,  attn_proj_w, 1, Cn, 0, 0,  XA, Cn, 1, 0, 0,
             Bn * TAn, Cn, Cn, 1, 1, attn_proj_b, 0, 4, nullptr, XA, nullptr, 0.f);
    ln_k<<<Bn * TAn, 256>>>(XA, HLN, ln2_w, ln2_b);
    run_gemm(HLN, Cn, 1, 0, 0,  fc_w, 1, Cn, 0, 0,  FC, 4 * Cn, 1, 0, 0,
             Bn * TAn, 4 * Cn, Cn, 1, 1, fc_b, 0, 2, nullptr, nullptr, nullptr, 0.f);
    run_gemm(FC, 4 * Cn, 1, 0, 0,  mlp_proj_w, 1, 4 * Cn, 0, 0,  XA, Cn, 1, 0, 0,
             Bn * TAn, Cn, 4 * Cn, 1, 1, mlp_proj_b, 0, 4, nullptr, XA, nullptr, 0.f);
    copyout_k<<<(int)(((long long)Bn * Tn * Cn + 255) / 256), 256>>>(XA, OUT, out);
    run_gemm(OUT, Cn, 1, 0, 0,  k_w, 1, Cn, 0, 0,  KEY, Cn, 1, 0, 0,
             Bn * Tn, Cn, Cn, 1, 1, k_b, 0, 0, nullptr, nullptr, nullptr, 0.f);
    run_gemm(OUT, Cn, 1, 0, 0,  v_w, 1, Cn, 0, 0,  VAL, Cn, 1, 0, 0,
             Bn * Tn, Cn, Cn, 1, 1, v_b, 0, 0, nullptr, nullptr, nullptr, 0.f);
    run_gemm(KEY, Cn, 1, TC, 0,  mem_w0, 1, Cn, HC, 0,  HH, HIDn, 1, TH, 0,
             Tn, HIDn, Cn, Bn, 1, mem_b0, HIDn, 1, PRE, nullptr, nullptr, 0.f);
    run_gemm(HH, HIDn, 1, TH, 0,  mem_w1, 1, HIDn, CH, 0,  DPR, Cn, 1, TC, 0,
             Tn, Cn, HIDn, Bn, 1, mem_b1, Cn, 5, nullptr, VAL, nullptr,
             2.f / (float)(Tn * Cn));
    run_gemm(DPR, 1, Cn, TC, 0,  HH, HIDn, 1, TH, 0,  out + o_nw1, HIDn, 1, CH, 0,
             Cn, HIDn, Tn, Bn, 1, nullptr, 0, 7, out + o_nmw1, mem_w1, mom_w1, 0.f);
    run_gemm(DPR, Cn, 1, TC, 0,  mem_w1, HIDn, 1, CH, 0,  DHH, HIDn, 1, TH, 0,
             Tn, HIDn, Cn, Bn, 1, nullptr, 0, 6, nullptr, PRE, nullptr, 0.f);
    run_gemm(DHH, 1, HIDn, TH, 0,  KEY, Cn, 1, TC, 0,  out + o_nw0, Cn, 1, HC, 0,
             HIDn, Cn, Tn, Bn, 1, nullptr, 0, 7, out + o_nmw0, mem_w0, mom_w0, 0.f);
    colsum_part_k<<<(SLICES * Bn * Cn + 255) / 256, 256>>>(DPR, P1, Cn);
    colsum_fin_k<<<(Bn * Cn + 255) / 256, 256>>>(P1, mem_b1, mom_b1,
                                                 out + o_nb1, out + o_nmb1, Bn * Cn);
    colsum_part_k<<<(SLICES * Bn * HIDn + 255) / 256, 256>>>(DHH, P0, HIDn);
    colsum_fin_k<<<(Bn * HIDn + 255) / 256, 256>>>(P0, mem_b0, mom_b0,
                                                   out + o_nb0, out + o_nmb0, Bn * HIDn);
    (void)in_sizes; (void)n_in; (void)out_size;
}